// round 16
// baseline (speedup 1.0000x reference)
#include <cuda_runtime.h>
#include <cuda_bf16.h>
#include <stdint.h>
#include <math.h>

#define D        27
#define QB       512
#define NCLS     11
#define KNN      3
#define SLABS    148
#define GROUPS   8                    // query groups of 64
#define TILE     64
#define GPITCH   128                  // gmem bytes per formatted row (2 pairs)
#define SPITCH   192                  // smem pitch for A staging (conflict-free)
#define NPMAX    409600
#define SMEM_TOT (64 * SPITCH + 64)

// ---------------- static device scratch ------------------------------------
__device__ unsigned int g_scale_bits[D];
__device__ float        g_qm[QB * D];     // -2 * scaled query
__device__ float        g_qn[QB];
__device__ float2       g_part[(size_t)QB * SLABS * KNN];
__device__ unsigned int g_done[GROUPS];   // last-CTA counters (self-resetting)
__device__ __align__(16) uint8_t g_btiles[(size_t)NPMAX * GPITCH];

// ---------------- helpers ----------------------------------------------------
__device__ __forceinline__ uint32_t smem_u32(const void* p) {
    uint32_t a;
    asm("{ .reg .u64 t; cvta.to.shared.u64 t, %1; cvt.u32.u64 %0, t; }" : "=r"(a) : "l"(p));
    return a;
}
__device__ __forceinline__ void lds128(uint32_t& x, uint32_t& y, uint32_t& z, uint32_t& w, uint32_t a) {
    asm volatile("ld.shared.v4.b32 {%0,%1,%2,%3}, [%4];"
                 : "=r"(x), "=r"(y), "=r"(z), "=r"(w) : "r"(a));
}
__device__ __forceinline__ void sts128(uint32_t a, uint32_t w0, uint32_t w1, uint32_t w2, uint32_t w3) {
    asm volatile("st.shared.v4.b32 [%0], {%1,%2,%3,%4};"
                 :: "r"(a), "r"(w0), "r"(w1), "r"(w2), "r"(w3) : "memory");
}
__device__ __forceinline__ uint32_t pk(__nv_bfloat16 a, __nv_bfloat16 b) {
    unsigned short x = *(unsigned short*)&a, y = *(unsigned short*)&b;
    return (uint32_t)x | ((uint32_t)y << 16);
}

#define MMA(d0,d1,d2,d3, A0,A1,A2,A3, B0,B1) \
    asm volatile("mma.sync.aligned.m16n8k16.row.col.f32.bf16.bf16.f32 " \
        "{%0,%1,%2,%3}, {%4,%5,%6,%7}, {%8,%9}, {%0,%1,%2,%3};" \
        : "+f"(d0), "+f"(d1), "+f"(d2), "+f"(d3) \
        : "r"(A0), "r"(A1), "r"(A2), "r"(A3), "r"(B0), "r"(B1))

#define MMA0(d0,d1,d2,d3, A0,A1,A2,A3, B0,B1) \
    asm volatile("mma.sync.aligned.m16n8k16.row.col.f32.bf16.bf16.f32 " \
        "{%0,%1,%2,%3}, {%4,%5,%6,%7}, {%8,%9}, {%10,%11,%12,%13};" \
        : "=f"(d0), "=f"(d1), "=f"(d2), "=f"(d3) \
        : "r"(A0), "r"(A1), "r"(A2), "r"(A3), "r"(B0), "r"(B1), \
          "f"(0.f), "f"(0.f), "f"(0.f), "f"(0.f))

// top-3 insert with lower-index tie-break
__device__ __forceinline__ void ins3(float v, int ix,
                                     float& r0, int& y0, float& r1, int& y1,
                                     float& r2, int& y2) {
    if (v < r2 || (v == r2 && ix < y2)) {
        if (v < r1 || (v == r1 && ix < y1)) {
            r2 = r1; y2 = y1;
            if (v < r0 || (v == r0 && ix < y0)) { r1 = r0; y1 = y0; r0 = v; y0 = ix; }
            else                                 { r1 = v;  y1 = ix; }
        } else { r2 = v; y2 = ix; }
    }
}

// ---------------- k_scale: per-column max|x|, float4 loads --------------------
__global__ void k_scale(const float* __restrict__ tf, int n) {
    __shared__ unsigned int sm[D];
    const int tid = threadIdx.x;
    if (tid < D) sm[tid] = 0u;
    __syncthreads();

    const int nv = n >> 2;
    int vi = blockIdx.x * blockDim.x + tid;
    const int vstride = gridDim.x * blockDim.x;    // x4 elements % 27 == 0
    const int e0 = vi * 4;
    const int c0 = e0 % D, c1 = (e0 + 1) % D, c2 = (e0 + 2) % D, c3 = (e0 + 3) % D;
    float m0 = 0.f, m1 = 0.f, m2 = 0.f, m3 = 0.f;
    const float4* tf4 = (const float4*)tf;
    for (; vi < nv; vi += vstride) {
        float4 v = __ldg(tf4 + vi);
        m0 = fmaxf(m0, fabsf(v.x));
        m1 = fmaxf(m1, fabsf(v.y));
        m2 = fmaxf(m2, fabsf(v.z));
        m3 = fmaxf(m3, fabsf(v.w));
    }
    atomicMax(&sm[c0], __float_as_uint(m0));
    atomicMax(&sm[c1], __float_as_uint(m1));
    atomicMax(&sm[c2], __float_as_uint(m2));
    atomicMax(&sm[c3], __float_as_uint(m3));
    if (blockIdx.x == 0 && tid == 0) {
        for (int e = nv * 4; e < n; ++e)
            atomicMax(&sm[e % D], __float_as_uint(fabsf(tf[e])));
    }
    __syncthreads();
    if (tid < D) atomicMax(&g_scale_bits[tid], sm[tid]);
}

// ---------------- k_prep: format train set (and queries), 128 B per point -----
// Pair P0 @0:  even = hi[0:16], odd = hi[16:27] + xn_hi@k27 + xn_lo@k28
// Pair P1 @64: even = lo[0:16], odd = lo[16:27] + 0 + 0
__global__ void __launch_bounds__(128) k_prep(const float* __restrict__ tf,
                                              const float* __restrict__ query,
                                              int N, int NP) {
    __shared__ __align__(16) char buf[128 * 8 * 16];
    __shared__ float inv[D];
    float* st  = (float*)buf;
    uint4* pkm = (uint4*)buf;
    const int tid = threadIdx.x;
    const int p0  = blockIdx.x * 128;
    if (tid < D) {
        float s = __uint_as_float(g_scale_bits[tid]);
        inv[tid] = (s != 0.f) ? (1.f / s) : 0.f;
    }
    __syncthreads();

    if (blockIdx.x < 4) {
        const int q = blockIdx.x * 128 + tid;
        float qn = 0.f;
        #pragma unroll
        for (int d = 0; d < D; ++d) {
            float v = query[q * D + d] * inv[d];
            qn = fmaf(v, v, qn);
            g_qm[q * D + d] = -2.f * v;
        }
        g_qn[q] = qn;
    }

    if (p0 + 128 <= N) {
        const float4* src = (const float4*)(tf + (size_t)p0 * D);
        float4* dst4 = (float4*)st;
        #pragma unroll
        for (int k = 0; k < 7; ++k) {
            int i = tid + k * 128;
            if (i < 864) dst4[i] = src[i];
        }
    } else {
        const int lim = (N - p0) * D;
        for (int i = tid; i < 128 * D; i += 128)
            st[i] = (i < lim) ? tf[(size_t)p0 * D + i] : 0.f;
    }
    __syncthreads();

    const int p = p0 + tid;
    float v[27];
    float xn = 0.f;
    #pragma unroll
    for (int d = 0; d < D; ++d) {
        float x = st[tid * D + d] * inv[d];
        v[d] = x;
        xn = fmaf(x, x, xn);
    }
    if (p >= N) xn = 1e30f;

    __nv_bfloat16 hb[27], lb[27];
    #pragma unroll
    for (int d = 0; d < D; ++d) {
        hb[d] = __float2bfloat16(v[d]);
        lb[d] = __float2bfloat16(v[d] - __bfloat162float(hb[d]));
    }
    const __nv_bfloat16 zr = __float2bfloat16(0.f);
    __nv_bfloat16 xh = __float2bfloat16(xn);
    __nv_bfloat16 xl = __float2bfloat16(xn - __bfloat162float(xh));

    uint32_t hw0[8], lw0[8], hob[8], lob[8];
    #pragma unroll
    for (int j = 0; j < 8; ++j) {
        hw0[j] = pk(hb[2*j], hb[2*j+1]);
        lw0[j] = pk(lb[2*j], lb[2*j+1]);
    }
    #pragma unroll
    for (int j = 0; j < 5; ++j) {
        hob[j] = pk(hb[16+2*j], hb[17+2*j]);
        lob[j] = pk(lb[16+2*j], lb[17+2*j]);
    }
    hob[5] = pk(hb[26], xh); hob[6] = pk(xl, zr); hob[7] = 0;
    lob[5] = pk(lb[26], zr); lob[6] = 0;          lob[7] = 0;

    uint4 my[8];
    #pragma unroll
    for (int c = 0; c < 4; ++c) {
        my[c]     = make_uint4(hw0[c], hw0[c+4], hob[c], hob[c+4]);
        my[4 + c] = make_uint4(lw0[c], lw0[c+4], lob[c], lob[c+4]);
    }
    __syncthreads();
    if (p < NP) {
        #pragma unroll
        for (int i = 0; i < 8; ++i) pkm[tid * 8 + i] = my[i];
    }
    __syncthreads();

    const int npts = min(128, NP - p0);
    if (npts > 0) {
        uint4* gd = (uint4*)(g_btiles + (size_t)p0 * GPITCH);
        const int tot = npts * 8;
        for (int i = tid; i < tot; i += 128) gd[i] = pkm[i];
    }
}

// ---------------- main HMMA kernel + fused last-CTA reduction -----------------
__global__ void __launch_bounds__(128, 8)
k_hmma(int N, const float* __restrict__ labels, float* __restrict__ out) {
    extern __shared__ char smraw[];
    const uint32_t smb = smem_u32(smraw);
    const int tid  = threadIdx.x;
    const int w    = tid >> 5;
    const int lane = tid & 31;
    const int g    = lane >> 2;
    const int c    = lane & 3;
    const int qg   = blockIdx.x & 7;
    const int slab = blockIdx.x >> 3;
    const int qbase = qg * 64;
    const int nt = (N + TILE - 1) / TILE;

    // ---- stage A rows (64 queries, threads 0-63), pair layout in smem
    if (tid < 64) {
        const int q = qbase + tid;
        __nv_bfloat16 hi_[27], lo_[27];
        #pragma unroll
        for (int d = 0; d < D; ++d) {
            float v = g_qm[q * D + d];
            __nv_bfloat16 h = __float2bfloat16(v);
            hi_[d] = h;
            lo_[d] = __float2bfloat16(v - __bfloat162float(h));
        }
        const __nv_bfloat16 one = __float2bfloat16(1.f);
        const __nv_bfloat16 zr  = __float2bfloat16(0.f);
        uint32_t hw[8], lw[8], ho[8], lo2[8];
        #pragma unroll
        for (int j = 0; j < 8; ++j) {
            hw[j] = pk(hi_[2*j], hi_[2*j+1]);
            lw[j] = pk(lo_[2*j], lo_[2*j+1]);
        }
        #pragma unroll
        for (int j = 0; j < 5; ++j) {
            ho[j]  = pk(hi_[16+2*j], hi_[17+2*j]);
            lo2[j] = pk(lo_[16+2*j], lo_[17+2*j]);
        }
        ho[5]  = pk(hi_[26], one); ho[6]  = pk(one, zr); ho[7]  = 0;
        lo2[5] = pk(lo_[26], zr);  lo2[6] = 0;           lo2[7] = 0;
        const uint32_t rowa = smb + tid * SPITCH;
        #pragma unroll
        for (int cc = 0; cc < 4; ++cc) {
            sts128(rowa +      cc*16, hw[cc], hw[cc+4], ho[cc],  ho[cc+4]);
            sts128(rowa + 64 + cc*16, lw[cc], lw[cc+4], lo2[cc], lo2[cc+4]);
        }
    }
    __syncthreads();

    uint32_t A0[4], A1[4], A2[4], A3[4];
    {
        const uint32_t base = smb + (uint32_t)(w * 16 + g) * SPITCH + c * 16;
        lds128(A0[0], A2[0], A0[1], A2[1], base);
        lds128(A1[0], A3[0], A1[1], A3[1], base + 8 * SPITCH);
        lds128(A0[2], A2[2], A0[3], A2[3], base + 64);
        lds128(A1[2], A3[2], A1[3], A3[3], base + 64 + 8 * SPITCH);
    }

    const float INF = __int_as_float(0x7f800000);
    float t0[2], t1[2], t2[2];
    int   i0[2], i1[2], i2[2];
    #pragma unroll
    for (int s = 0; s < 2; ++s) { t0[s]=t1[s]=t2[s]=INF; i0[s]=i1[s]=i2[s]=0; }

    #define INS(v_, idx_, s_) do { \
        float _v = (v_); \
        if (_v < t2[s_]) { \
            int _ix = (idx_); \
            if (_v < t1[s_]) { \
                t2[s_] = t1[s_]; i2[s_] = i1[s_]; \
                if (_v < t0[s_]) { t1[s_]=t0[s_]; i1[s_]=i0[s_]; t0[s_]=_v; i0[s_]=_ix; } \
                else             { t1[s_]=_v; i1[s_]=_ix; } \
            } else { t2[s_] = _v; i2[s_] = _ix; } \
        } } while (0)
    #define INS2(da_, db_, s_) do { \
        if (fminf(da_, db_) < t2[s_]) { INS(da_, idx0, s_); INS(db_, idx0 + 1, s_); } } while (0)

    // ---- main loop: stream B fragments straight from L2/L1 (no smem, no bars)
    for (int t = slab; t < nt; t += SLABS) {
        const int tb = t * TILE;
        int idx0 = tb + 2 * c;
        const uint4* frag = (const uint4*)(g_btiles + (size_t)tb * GPITCH + g * GPITCH + c * 16);
        #pragma unroll 4
        for (int j = 0; j < 8; ++j) {
            const uint4 b0 = __ldg(frag);            // P0: hi_e / hi_o(+xn)
            const uint4 b1 = __ldg(frag + 4);        // P1: lo_e / lo_o(+0)
            float d0,d1,d2,d3;
            MMA0(d0,d1,d2,d3, A0[0],A1[0],A2[0],A3[0], b0.x,b0.y);
            MMA (d0,d1,d2,d3, A0[1],A1[1],A2[1],A3[1], b0.z,b0.w);
            MMA (d0,d1,d2,d3, A0[2],A1[2],A2[2],A3[2], b0.x,b0.y);
            MMA (d0,d1,d2,d3, A0[3],A1[3],A2[3],A3[3], b0.z,b0.w);
            MMA (d0,d1,d2,d3, A0[0],A1[0],A2[0],A3[0], b1.x,b1.y);
            MMA (d0,d1,d2,d3, A0[1],A1[1],A2[1],A3[1], b1.z,b1.w);

            INS2(d0, d1, 0);
            INS2(d2, d3, 1);
            frag += 8 * GPITCH / 16;
            idx0 += 8;
        }
    }
    #undef INS2
    #undef INS

    // ---- merge top-3 across the 4 lanes of each quad
    #pragma unroll
    for (int s = 0; s < 2; ++s) {
        #pragma unroll
        for (int off = 2; off > 0; off >>= 1) {
            float o0 = __shfl_down_sync(0xffffffffu, t0[s], off);
            float o1 = __shfl_down_sync(0xffffffffu, t1[s], off);
            float o2 = __shfl_down_sync(0xffffffffu, t2[s], off);
            int   z0 = __shfl_down_sync(0xffffffffu, i0[s], off);
            int   z1 = __shfl_down_sync(0xffffffffu, i1[s], off);
            int   z2 = __shfl_down_sync(0xffffffffu, i2[s], off);
            ins3(o0, z0, t0[s], i0[s], t1[s], i1[s], t2[s], i2[s]);
            ins3(o1, z1, t0[s], i0[s], t1[s], i1[s], t2[s], i2[s]);
            ins3(o2, z2, t0[s], i0[s], t1[s], i1[s], t2[s], i2[s]);
        }
    }
    if ((lane & 3) == 0) {
        #pragma unroll
        for (int s = 0; s < 2; ++s) {
            const int q = qbase + w * 16 + g + s * 8;
            float2* o = g_part + ((size_t)q * SLABS + slab) * KNN;
            o[0] = make_float2(t0[s], __int_as_float(i0[s]));
            o[1] = make_float2(t1[s], __int_as_float(i1[s]));
            o[2] = make_float2(t2[s], __int_as_float(i2[s]));
        }
    }

    // ---- last-CTA fused reduction (threadFenceReduction pattern) -------------
    __threadfence();
    __syncthreads();
    __shared__ unsigned int s_last;
    if (tid == 0)
        s_last = (atomicAdd(&g_done[qg], 1u) == SLABS - 1) ? 1u : 0u;
    __syncthreads();
    if (!s_last) return;
    if (tid == 0) g_done[qg] = 0;    // reset for next graph replay
    __threadfence();                 // acquire: all producers' partials visible

    // 4 warps reduce 64 queries (16 each), warp-per-query
    for (int qi = w; qi < 64; qi += 4) {
        const int q = qbase + qi;
        float b0 = INF, b1 = INF, b2 = INF;
        int   x0 = 0,   x1 = 0,   x2 = 0;
        const float2* p = g_part + (size_t)q * SLABS * KNN;
        for (int e = lane; e < SLABS * KNN; e += 32) {
            float2 v = p[e];
            ins3(v.x, __float_as_int(v.y), b0, x0, b1, x1, b2, x2);
        }
        #pragma unroll
        for (int off = 16; off > 0; off >>= 1) {
            float o0 = __shfl_down_sync(0xffffffffu, b0, off);
            float o1 = __shfl_down_sync(0xffffffffu, b1, off);
            float o2 = __shfl_down_sync(0xffffffffu, b2, off);
            int   z0 = __shfl_down_sync(0xffffffffu, x0, off);
            int   z1 = __shfl_down_sync(0xffffffffu, x1, off);
            int   z2 = __shfl_down_sync(0xffffffffu, x2, off);
            ins3(o0, z0, b0, x0, b1, x1, b2, x2);
            ins3(o1, z1, b0, x0, b1, x1, b2, x2);
            ins3(o2, z2, b0, x0, b1, x1, b2, x2);
        }
        if (lane == 0) {
            const float qn = g_qn[q];
            const float kd0 = sqrtf(fmaxf(b0 + qn, 0.f));
            const float kd1 = sqrtf(fmaxf(b1 + qn, 0.f));
            const float kd2 = sqrtf(fmaxf(b2 + qn, 0.f));
            out[q * KNN + 0] = kd0;
            out[q * KNN + 1] = kd1;
            out[q * KNN + 2] = kd2;

            const float w0 = (kd0 == 0.f) ? 1.f : kd0;
            const float w1 = (kd1 == 0.f) ? 1.f : kd1;
            const float w2 = (kd2 == 0.f) ? 1.f : kd2;
            const float* l0 = labels + (size_t)x0 * NCLS;
            const float* l1 = labels + (size_t)x1 * NCLS;
            const float* l2 = labels + (size_t)x2 * NCLS;

            float votes[NCLS];
            #pragma unroll
            for (int cc = 0; cc < NCLS; ++cc)
                votes[cc] = l0[cc] / w0 + l1[cc] / w1 + l2[cc] / w2;

            int am = 0; float bm = votes[0];
            #pragma unroll
            for (int cc = 1; cc < NCLS; ++cc)
                if (votes[cc] > bm) { bm = votes[cc]; am = cc; }

            const bool zero_hit = (kd0 == 0.f);
            float* ro = out + QB * KNN + q * NCLS;
            #pragma unroll
            for (int cc = 0; cc < NCLS; ++cc)
                ro[cc] = zero_hit ? l0[cc] : ((cc == am) ? 1.f : 0.f);
        }
    }
}

// ---------------- launch --------------------------------------------------------
extern "C" void kernel_launch(void* const* d_in, const int* in_sizes, int n_in,
                              void* d_out, int out_size) {
    const float* query = (const float*)d_in[0];
    const float* tf    = (const float*)d_in[1];
    const float* tl    = (const float*)d_in[2];
    float* out = (float*)d_out;
    const int n_elems = in_sizes[1];
    const int N = n_elems / D;
    const int nt = (N + TILE - 1) / TILE;
    const int NP = nt * TILE;

    k_scale <<<888, 216>>>(tf, n_elems);
    k_prep  <<<(NP + 127) / 128, 128>>>(tf, query, N, NP);
    k_hmma  <<<SLABS * GROUPS, 128, SMEM_TOT>>>(N, tl, out);
}

// round 17
// speedup vs baseline: 2.3099x; 2.3099x over previous
#include <cuda_runtime.h>
#include <cuda_bf16.h>
#include <stdint.h>
#include <math.h>

#define D        27
#define QB       512
#define NCLS     11
#define KNN      3
#define SLABS    148
#define GROUPS   8                    // query groups of 64
#define TILE     64
#define GPITCH   128                  // gmem bytes per formatted row (2 pairs)
#define SPITCH   192                  // smem pitch for A staging (conflict-free)
#define NPMAX    409600
#define SMEM_TOT (64 * SPITCH + 64)

// ---------------- static device scratch ------------------------------------
__device__ unsigned int g_scale_bits[D];
__device__ float        g_qm[QB * D];     // -2 * scaled query
__device__ float        g_qn[QB];
__device__ float2       g_part[(size_t)QB * SLABS * KNN];
__device__ __align__(16) uint8_t g_btiles[(size_t)NPMAX * GPITCH];

// ---------------- helpers ----------------------------------------------------
__device__ __forceinline__ uint32_t smem_u32(const void* p) {
    uint32_t a;
    asm("{ .reg .u64 t; cvta.to.shared.u64 t, %1; cvt.u32.u64 %0, t; }" : "=r"(a) : "l"(p));
    return a;
}
__device__ __forceinline__ void lds128(uint32_t& x, uint32_t& y, uint32_t& z, uint32_t& w, uint32_t a) {
    asm volatile("ld.shared.v4.b32 {%0,%1,%2,%3}, [%4];"
                 : "=r"(x), "=r"(y), "=r"(z), "=r"(w) : "r"(a));
}
__device__ __forceinline__ void sts128(uint32_t a, uint32_t w0, uint32_t w1, uint32_t w2, uint32_t w3) {
    asm volatile("st.shared.v4.b32 [%0], {%1,%2,%3,%4};"
                 :: "r"(a), "r"(w0), "r"(w1), "r"(w2), "r"(w3) : "memory");
}
__device__ __forceinline__ uint32_t pk(__nv_bfloat16 a, __nv_bfloat16 b) {
    unsigned short x = *(unsigned short*)&a, y = *(unsigned short*)&b;
    return (uint32_t)x | ((uint32_t)y << 16);
}

#define MMA(d0,d1,d2,d3, A0,A1,A2,A3, B0,B1) \
    asm volatile("mma.sync.aligned.m16n8k16.row.col.f32.bf16.bf16.f32 " \
        "{%0,%1,%2,%3}, {%4,%5,%6,%7}, {%8,%9}, {%0,%1,%2,%3};" \
        : "+f"(d0), "+f"(d1), "+f"(d2), "+f"(d3) \
        : "r"(A0), "r"(A1), "r"(A2), "r"(A3), "r"(B0), "r"(B1))

#define MMA0(d0,d1,d2,d3, A0,A1,A2,A3, B0,B1) \
    asm volatile("mma.sync.aligned.m16n8k16.row.col.f32.bf16.bf16.f32 " \
        "{%0,%1,%2,%3}, {%4,%5,%6,%7}, {%8,%9}, {%10,%11,%12,%13};" \
        : "=f"(d0), "=f"(d1), "=f"(d2), "=f"(d3) \
        : "r"(A0), "r"(A1), "r"(A2), "r"(A3), "r"(B0), "r"(B1), \
          "f"(0.f), "f"(0.f), "f"(0.f), "f"(0.f))

// ---------------- k_scale: per-column max|x|, float4 loads --------------------
// grid 888 x 216: stride x4 elements == 0 mod 27 -> loop-invariant columns.
__global__ void k_scale(const float* __restrict__ tf, int n) {
    __shared__ unsigned int sm[D];
    const int tid = threadIdx.x;
    if (tid < D) sm[tid] = 0u;
    __syncthreads();

    const int nv = n >> 2;
    int vi = blockIdx.x * blockDim.x + tid;
    const int vstride = gridDim.x * blockDim.x;
    const int e0 = vi * 4;
    const int c0 = e0 % D, c1 = (e0 + 1) % D, c2 = (e0 + 2) % D, c3 = (e0 + 3) % D;
    float m0 = 0.f, m1 = 0.f, m2 = 0.f, m3 = 0.f;
    const float4* tf4 = (const float4*)tf;
    for (; vi < nv; vi += vstride) {
        float4 v = __ldg(tf4 + vi);
        m0 = fmaxf(m0, fabsf(v.x));
        m1 = fmaxf(m1, fabsf(v.y));
        m2 = fmaxf(m2, fabsf(v.z));
        m3 = fmaxf(m3, fabsf(v.w));
    }
    atomicMax(&sm[c0], __float_as_uint(m0));
    atomicMax(&sm[c1], __float_as_uint(m1));
    atomicMax(&sm[c2], __float_as_uint(m2));
    atomicMax(&sm[c3], __float_as_uint(m3));
    if (blockIdx.x == 0 && tid == 0) {
        for (int e = nv * 4; e < n; ++e)
            atomicMax(&sm[e % D], __float_as_uint(fabsf(tf[e])));
    }
    __syncthreads();
    if (tid < D) atomicMax(&g_scale_bits[tid], sm[tid]);
}

// ---------------- k_prep: format train set (and queries), 128 B per point -----
// Pair P0 @0:  even = hi[0:16], odd = hi[16:27] + xn_hi@k27 + xn_lo@k28
// Pair P1 @64: even = lo[0:16], odd = lo[16:27] + 0 + 0
// chunk c of a pair = {we[c], we[c+4], wo[c], wo[c+4]}  (16 B each, 4 per pair)
__global__ void __launch_bounds__(128) k_prep(const float* __restrict__ tf,
                                              const float* __restrict__ query,
                                              int N, int NP) {
    __shared__ __align__(16) char buf[128 * 8 * 16];    // 16384 B union
    __shared__ float inv[D];
    float* st  = (float*)buf;          // phase 1: 128*27 floats (13824 B)
    uint4* pkm = (uint4*)buf;          // phase 3: 128*8 uint4
    const int tid = threadIdx.x;
    const int p0  = blockIdx.x * 128;
    if (tid < D) {
        float s = __uint_as_float(g_scale_bits[tid]);
        inv[tid] = (s != 0.f) ? (1.f / s) : 0.f;   // divide_no_nan
    }
    __syncthreads();

    // ---- query side (blocks 0-3; 128 queries each)
    if (blockIdx.x < 4) {
        const int q = blockIdx.x * 128 + tid;
        float qn = 0.f;
        #pragma unroll
        for (int d = 0; d < D; ++d) {
            float v = query[q * D + d] * inv[d];
            qn = fmaf(v, v, qn);
            g_qm[q * D + d] = -2.f * v;
        }
        g_qn[q] = qn;
    }

    // ---- phase 1: coalesced read into linear smem
    if (p0 + 128 <= N) {
        const float4* src = (const float4*)(tf + (size_t)p0 * D);
        float4* dst4 = (float4*)st;
        #pragma unroll
        for (int k = 0; k < 7; ++k) {
            int i = tid + k * 128;
            if (i < 864) dst4[i] = src[i];
        }
    } else {
        const int lim = (N - p0) * D;
        for (int i = tid; i < 128 * D; i += 128)
            st[i] = (i < lim) ? tf[(size_t)p0 * D + i] : 0.f;
    }
    __syncthreads();

    // ---- phase 2: per-thread scale + split + pack (registers only)
    const int p = p0 + tid;
    float v[27];
    float xn = 0.f;
    #pragma unroll
    for (int d = 0; d < D; ++d) {
        float x = st[tid * D + d] * inv[d];   // stride 27 -> conflict-free
        v[d] = x;
        xn = fmaf(x, x, xn);
    }
    if (p >= N) xn = 1e30f;     // padding rows never win top-3

    __nv_bfloat16 hb[27], lb[27];
    #pragma unroll
    for (int d = 0; d < D; ++d) {
        hb[d] = __float2bfloat16(v[d]);
        lb[d] = __float2bfloat16(v[d] - __bfloat162float(hb[d]));
    }
    const __nv_bfloat16 zr = __float2bfloat16(0.f);
    __nv_bfloat16 xh = __float2bfloat16(xn);
    __nv_bfloat16 xl = __float2bfloat16(xn - __bfloat162float(xh));

    uint32_t hw0[8], lw0[8], hob[8], lob[8];
    #pragma unroll
    for (int j = 0; j < 8; ++j) {
        hw0[j] = pk(hb[2*j], hb[2*j+1]);
        lw0[j] = pk(lb[2*j], lb[2*j+1]);
    }
    #pragma unroll
    for (int j = 0; j < 5; ++j) {
        hob[j] = pk(hb[16+2*j], hb[17+2*j]);
        lob[j] = pk(lb[16+2*j], lb[17+2*j]);
    }
    hob[5] = pk(hb[26], xh); hob[6] = pk(xl, zr); hob[7] = 0;   // xn folded
    lob[5] = pk(lb[26], zr); lob[6] = 0;          lob[7] = 0;   // zeros at k27/28

    uint4 my[8];
    #pragma unroll
    for (int c = 0; c < 4; ++c) {
        my[c]     = make_uint4(hw0[c], hw0[c+4], hob[c], hob[c+4]);  // P0 (hi_e, hi_o+xn)
        my[4 + c] = make_uint4(lw0[c], lw0[c+4], lob[c], lob[c+4]);  // P1 (lo_e, lo_o+0)
    }
    __syncthreads();   // all st reads done before pkm overwrites buf
    if (p < NP) {
        #pragma unroll
        for (int i = 0; i < 8; ++i) pkm[tid * 8 + i] = my[i];
    }
    __syncthreads();

    // ---- phase 3: coalesced STG.128 stream of the block's 16 KB
    const int npts = min(128, NP - p0);
    if (npts > 0) {
        uint4* gd = (uint4*)(g_btiles + (size_t)p0 * GPITCH);
        const int tot = npts * 8;
        for (int i = tid; i < tot; i += 128) gd[i] = pkm[i];
    }
}

// ---------------- main HMMA kernel: B streamed from L2 via LDG, no barriers ---
__global__ void __launch_bounds__(128, 8)
k_hmma(int N) {
    extern __shared__ char smraw[];
    const uint32_t smb = smem_u32(smraw);
    const int tid  = threadIdx.x;
    const int w    = tid >> 5;
    const int lane = tid & 31;
    const int g    = lane >> 2;
    const int c    = lane & 3;
    const int qg   = blockIdx.x & 7;
    const int slab = blockIdx.x >> 3;
    const int qbase = qg * 64;
    const int nt = (N + TILE - 1) / TILE;

    // ---- stage A rows (64 queries, threads 0-63), pair layout in smem
    // A P0 = (hq_e, hq_o + ones@k27/28); A P1 = (lq_e, lq_o + zeros)
    if (tid < 64) {
        const int q = qbase + tid;
        __nv_bfloat16 hi_[27], lo_[27];
        #pragma unroll
        for (int d = 0; d < D; ++d) {
            float v = g_qm[q * D + d];
            __nv_bfloat16 h = __float2bfloat16(v);
            hi_[d] = h;
            lo_[d] = __float2bfloat16(v - __bfloat162float(h));
        }
        const __nv_bfloat16 one = __float2bfloat16(1.f);
        const __nv_bfloat16 zr  = __float2bfloat16(0.f);
        uint32_t hw[8], lw[8], ho[8], lo2[8];
        #pragma unroll
        for (int j = 0; j < 8; ++j) {
            hw[j] = pk(hi_[2*j], hi_[2*j+1]);
            lw[j] = pk(lo_[2*j], lo_[2*j+1]);
        }
        #pragma unroll
        for (int j = 0; j < 5; ++j) {
            ho[j]  = pk(hi_[16+2*j], hi_[17+2*j]);
            lo2[j] = pk(lo_[16+2*j], lo_[17+2*j]);
        }
        ho[5]  = pk(hi_[26], one); ho[6]  = pk(one, zr); ho[7]  = 0;  // ones pick up xn
        lo2[5] = pk(lo_[26], zr);  lo2[6] = 0;           lo2[7] = 0;  // zeros (xn once)
        const uint32_t rowa = smb + tid * SPITCH;
        #pragma unroll
        for (int cc = 0; cc < 4; ++cc) {
            sts128(rowa +      cc*16, hw[cc], hw[cc+4], ho[cc],  ho[cc+4]);  // P0
            sts128(rowa + 64 + cc*16, lw[cc], lw[cc+4], lo2[cc], lo2[cc+4]); // P1
        }
    }
    __syncthreads();

    // ---- persistent A fragments: 4 sets (0=hi_e 1=hi_o+ones 2=lo_e 3=lo_o)
    uint32_t A0[4], A1[4], A2[4], A3[4];
    {
        const uint32_t base = smb + (uint32_t)(w * 16 + g) * SPITCH + c * 16;
        lds128(A0[0], A2[0], A0[1], A2[1], base);
        lds128(A1[0], A3[0], A1[1], A3[1], base + 8 * SPITCH);
        lds128(A0[2], A2[2], A0[3], A2[3], base + 64);
        lds128(A1[2], A3[2], A1[3], A3[3], base + 64 + 8 * SPITCH);
    }

    const float INF = __int_as_float(0x7f800000);
    float t0[2], t1[2], t2[2];
    int   i0[2], i1[2], i2[2];
    #pragma unroll
    for (int s = 0; s < 2; ++s) { t0[s]=t1[s]=t2[s]=INF; i0[s]=i1[s]=i2[s]=0; }

    #define INS(v_, idx_, s_) do { \
        float _v = (v_); \
        if (_v < t2[s_]) { \
            int _ix = (idx_); \
            if (_v < t1[s_]) { \
                t2[s_] = t1[s_]; i2[s_] = i1[s_]; \
                if (_v < t0[s_]) { t1[s_]=t0[s_]; i1[s_]=i0[s_]; t0[s_]=_v; i0[s_]=_ix; } \
                else             { t1[s_]=_v; i1[s_]=_ix; } \
            } else { t2[s_] = _v; i2[s_] = _ix; } \
        } } while (0)
    #define INS2(da_, db_, s_) do { \
        if (fminf(da_, db_) < t2[s_]) { INS(da_, idx0, s_); INS(db_, idx0 + 1, s_); } } while (0)

    // ---- main loop: stream B fragments straight from L2/L1 (no smem, no bars)
    for (int t = slab; t < nt; t += SLABS) {
        const int tb = t * TILE;
        int idx0 = tb + 2 * c;
        const uint4* frag = (const uint4*)(g_btiles + (size_t)tb * GPITCH + g * GPITCH + c * 16);
        #pragma unroll 4
        for (int j = 0; j < 8; ++j) {
            const uint4 b0 = __ldg(frag);            // P0: hi_e / hi_o(+xn)
            const uint4 b1 = __ldg(frag + 4);        // P1: lo_e / lo_o(+0)
            float d0,d1,d2,d3;
            MMA0(d0,d1,d2,d3, A0[0],A1[0],A2[0],A3[0], b0.x,b0.y);   // hq.hx
            MMA (d0,d1,d2,d3, A0[1],A1[1],A2[1],A3[1], b0.z,b0.w);   // hq.hx tail + 1*xn
            MMA (d0,d1,d2,d3, A0[2],A1[2],A2[2],A3[2], b0.x,b0.y);   // lq.hx
            MMA (d0,d1,d2,d3, A0[3],A1[3],A2[3],A3[3], b0.z,b0.w);   // lq.hx tail + 0*xn
            MMA (d0,d1,d2,d3, A0[0],A1[0],A2[0],A3[0], b1.x,b1.y);   // hq.lx
            MMA (d0,d1,d2,d3, A0[1],A1[1],A2[1],A3[1], b1.z,b1.w);   // hq.lx tail + 1*0

            INS2(d0, d1, 0);     // row g
            INS2(d2, d3, 1);     // row g+8
            frag += 8 * GPITCH / 16;   // next 8 rows
            idx0 += 8;
        }
    }
    #undef INS2
    #undef INS

    // ---- merge top-3 across the 4 lanes of each quad (same queries, disjoint cols)
    #pragma unroll
    for (int s = 0; s < 2; ++s) {
        #pragma unroll
        for (int off = 2; off > 0; off >>= 1) {
            float o0 = __shfl_down_sync(0xffffffffu, t0[s], off);
            float o1 = __shfl_down_sync(0xffffffffu, t1[s], off);
            float o2 = __shfl_down_sync(0xffffffffu, t2[s], off);
            int   z0 = __shfl_down_sync(0xffffffffu, i0[s], off);
            int   z1 = __shfl_down_sync(0xffffffffu, i1[s], off);
            int   z2 = __shfl_down_sync(0xffffffffu, i2[s], off);
            #define MINS(vv, zz) do { \
                float _v = (vv); int _z = (zz); \
                if (_v < t2[s] || (_v == t2[s] && _z < i2[s])) { \
                    if (_v < t1[s] || (_v == t1[s] && _z < i1[s])) { \
                        t2[s]=t1[s]; i2[s]=i1[s]; \
                        if (_v < t0[s] || (_v == t0[s] && _z < i0[s])) { t1[s]=t0[s]; i1[s]=i0[s]; t0[s]=_v; i0[s]=_z; } \
                        else { t1[s]=_v; i1[s]=_z; } \
                    } else { t2[s]=_v; i2[s]=_z; } \
                } } while (0)
            MINS(o0, z0); MINS(o1, z1); MINS(o2, z2);
            #undef MINS
        }
    }
    if ((lane & 3) == 0) {
        #pragma unroll
        for (int s = 0; s < 2; ++s) {
            const int q = qbase + w * 16 + g + s * 8;
            float2* o = g_part + ((size_t)q * SLABS + slab) * KNN;
            o[0] = make_float2(t0[s], __int_as_float(i0[s]));
            o[1] = make_float2(t1[s], __int_as_float(i1[s]));
            o[2] = make_float2(t2[s], __int_as_float(i2[s]));
        }
    }
}

// ---------------- merge + vote (block-per-query, vectorized scan) -------------
__device__ __forceinline__ void ins3(float v, int ix,
                                     float& r0, int& y0, float& r1, int& y1,
                                     float& r2, int& y2) {
    if (v < r2 || (v == r2 && ix < y2)) {
        if (v < r1 || (v == r1 && ix < y1)) {
            r2 = r1; y2 = y1;
            if (v < r0 || (v == r0 && ix < y0)) { r1 = r0; y1 = y0; r0 = v; y0 = ix; }
            else                                 { r1 = v;  y1 = ix; }
        } else { r2 = v; y2 = ix; }
    }
}

__global__ void k_reduce(const float* __restrict__ labels, float* __restrict__ out) {
    const int q    = blockIdx.x;
    const int tid  = threadIdx.x;   // 128
    const int lane = tid & 31;
    const int wid  = tid >> 5;
    __shared__ float sd[12];
    __shared__ int   si[12];
    const float INF = __int_as_float(0x7f800000);

    float b0 = INF, b1 = INF, b2 = INF;
    int   x0 = 0,   x1 = 0,   x2 = 0;
    // per-query partial array: 444*3 = 1332 float2 = 666 float4 (16B-aligned)
    const float4* p4 = (const float4*)(g_part + (size_t)q * SLABS * KNN);
    for (int e = tid; e < (SLABS * KNN) / 2; e += 128) {
        float4 v = __ldg(p4 + e);
        ins3(v.x, __float_as_int(v.y), b0, x0, b1, x1, b2, x2);
        ins3(v.z, __float_as_int(v.w), b0, x0, b1, x1, b2, x2);
    }
    #pragma unroll
    for (int off = 16; off > 0; off >>= 1) {
        float o0 = __shfl_down_sync(0xffffffffu, b0, off);
        float o1 = __shfl_down_sync(0xffffffffu, b1, off);
        float o2 = __shfl_down_sync(0xffffffffu, b2, off);
        int   z0 = __shfl_down_sync(0xffffffffu, x0, off);
        int   z1 = __shfl_down_sync(0xffffffffu, x1, off);
        int   z2 = __shfl_down_sync(0xffffffffu, x2, off);
        ins3(o0, z0, b0, x0, b1, x1, b2, x2);
        ins3(o1, z1, b0, x0, b1, x1, b2, x2);
        ins3(o2, z2, b0, x0, b1, x1, b2, x2);
    }
    if (lane == 0) {
        sd[wid * 3 + 0] = b0; si[wid * 3 + 0] = x0;
        sd[wid * 3 + 1] = b1; si[wid * 3 + 1] = x1;
        sd[wid * 3 + 2] = b2; si[wid * 3 + 2] = x2;
    }
    __syncthreads();

    if (tid == 0) {
        float r0 = sd[0], r1 = sd[1], r2 = sd[2];
        int   y0 = si[0], y1 = si[1], y2 = si[2];
        #pragma unroll
        for (int e = 3; e < 12; ++e) ins3(sd[e], si[e], r0, y0, r1, y1, r2, y2);

        const float qn = g_qn[q];
        const float kd0 = sqrtf(fmaxf(r0 + qn, 0.f));
        const float kd1 = sqrtf(fmaxf(r1 + qn, 0.f));
        const float kd2 = sqrtf(fmaxf(r2 + qn, 0.f));
        out[q * KNN + 0] = kd0;
        out[q * KNN + 1] = kd1;
        out[q * KNN + 2] = kd2;

        const float w0 = (kd0 == 0.f) ? 1.f : kd0;
        const float w1 = (kd1 == 0.f) ? 1.f : kd1;
        const float w2 = (kd2 == 0.f) ? 1.f : kd2;
        const float* l0 = labels + (size_t)y0 * NCLS;
        const float* l1 = labels + (size_t)y1 * NCLS;
        const float* l2 = labels + (size_t)y2 * NCLS;

        float votes[NCLS];
        #pragma unroll
        for (int cc = 0; cc < NCLS; ++cc)
            votes[cc] = l0[cc] / w0 + l1[cc] / w1 + l2[cc] / w2;

        int am = 0; float bm = votes[0];
        #pragma unroll
        for (int cc = 1; cc < NCLS; ++cc)
            if (votes[cc] > bm) { bm = votes[cc]; am = cc; }

        const bool zero_hit = (kd0 == 0.f);
        float* ro = out + QB * KNN + q * NCLS;
        #pragma unroll
        for (int cc = 0; cc < NCLS; ++cc)
            ro[cc] = zero_hit ? l0[cc] : ((cc == am) ? 1.f : 0.f);
    }
}

// ---------------- launch --------------------------------------------------------
extern "C" void kernel_launch(void* const* d_in, const int* in_sizes, int n_in,
                              void* d_out, int out_size) {
    const float* query = (const float*)d_in[0];
    const float* tf    = (const float*)d_in[1];
    const float* tl    = (const float*)d_in[2];
    float* out = (float*)d_out;
    const int n_elems = in_sizes[1];
    const int N = n_elems / D;
    const int nt = (N + TILE - 1) / TILE;
    const int NP = nt * TILE;

    k_scale <<<888, 216>>>(tf, n_elems);
    k_prep  <<<(NP + 127) / 128, 128>>>(tf, query, N, NP);
    k_hmma  <<<SLABS * GROUPS, 128, SMEM_TOT>>>(N);
    k_reduce<<<QB,  128>>>(tl, out);
}